// round 1
// baseline (speedup 1.0000x reference)
#include <cuda_runtime.h>
#include <cstdint>

#define D_FEAT   64
#define D_OUT    64
#define MAX_NODES 50000
#define ROWS_PER_BLOCK 32
#define XT_STRIDE 36   // padded to avoid bank conflicts, 144B rows keep float4 alignment

// Scratch: per-node projections (graph-capturable, no allocs)
__device__ float g_Psrc[MAX_NODES * D_OUT];
__device__ float g_Pdst[MAX_NODES * D_OUT];

// ---------------------------------------------------------------------------
// Kernel 1: per-node projections
//   Psrc[n][j] = sum_{k<64} x[n][k] * W[k][j]        + b[j]
//   Pdst[n][j] = sum_{k<64} x[n][k] * W[64+k][j]
// 256 threads, 32 rows per block. Register tile: 4 rows x 2 cols x {src,dst}.
// ---------------------------------------------------------------------------
__global__ __launch_bounds__(256) void node_project_kernel(
    const float* __restrict__ x,
    const float* __restrict__ W,
    const float* __restrict__ b,
    int n_nodes)
{
    __shared__ float Wsh[2 * D_FEAT * D_OUT];       // 128x64 fp32 = 32 KB
    __shared__ float xT[D_FEAT * XT_STRIDE];        // transposed x tile, padded

    const int tid  = threadIdx.x;
    const int row0 = blockIdx.x * ROWS_PER_BLOCK;

    // Stage W (row-major [128][64])
    #pragma unroll 4
    for (int i = tid; i < 2 * D_FEAT * D_OUT; i += 256)
        Wsh[i] = W[i];

    // Stage x tile transposed: xT[k][r] = x[row0+r][k]
    // Global read coalesced (consecutive lanes -> consecutive cols).
    for (int i = tid; i < ROWS_PER_BLOCK * D_FEAT; i += 256) {
        const int r = i >> 6;        // 0..31
        const int c = i & 63;        // 0..63
        float v = 0.0f;
        if (row0 + r < n_nodes) v = x[(row0 + r) * D_FEAT + c];
        xT[c * XT_STRIDE + r] = v;
    }
    __syncthreads();

    // Thread tile: rows r0..r0+3 (tid&7), cols c0..c0+1 (tid>>3)
    const int r0 = (tid & 7) << 2;      // 0,4,...,28
    const int c0 = (tid >> 3) << 1;     // 0,2,...,62

    float accS[4][2] = {{0.f,0.f},{0.f,0.f},{0.f,0.f},{0.f,0.f}};
    float accD[4][2] = {{0.f,0.f},{0.f,0.f},{0.f,0.f},{0.f,0.f}};

    #pragma unroll 8
    for (int k = 0; k < D_FEAT; k++) {
        const float4 xv = *reinterpret_cast<const float4*>(&xT[k * XT_STRIDE + r0]);
        const float2 ws = *reinterpret_cast<const float2*>(&Wsh[k * D_OUT + c0]);
        const float2 wd = *reinterpret_cast<const float2*>(&Wsh[(D_FEAT + k) * D_OUT + c0]);
        const float xr[4] = {xv.x, xv.y, xv.z, xv.w};
        #pragma unroll
        for (int i = 0; i < 4; i++) {
            accS[i][0] += xr[i] * ws.x;
            accS[i][1] += xr[i] * ws.y;
            accD[i][0] += xr[i] * wd.x;
            accD[i][1] += xr[i] * wd.y;
        }
    }

    // Fold bias into Psrc so the edge kernel is a pure 2-gather add.
    const float2 bv = *reinterpret_cast<const float2*>(&b[c0]);

    #pragma unroll
    for (int i = 0; i < 4; i++) {
        const int row = row0 + r0 + i;
        if (row < n_nodes) {
            *reinterpret_cast<float2*>(&g_Psrc[row * D_OUT + c0]) =
                make_float2(accS[i][0] + bv.x, accS[i][1] + bv.y);
            *reinterpret_cast<float2*>(&g_Pdst[row * D_OUT + c0]) =
                make_float2(accD[i][0], accD[i][1]);
        }
    }
}

// ---------------------------------------------------------------------------
// Kernel 2: edge gather-add
//   out[e][:] = Psrc[src[e]][:] + Pdst[dst[e]][:]
// 16 threads per edge, float4 per thread. Psrc/Pdst are L2-resident (25.6 MB).
// ---------------------------------------------------------------------------
__global__ __launch_bounds__(256) void edge_gather_kernel(
    const int* __restrict__ src,
    const int* __restrict__ dst,
    const float* __restrict__ Psrc,
    const float* __restrict__ Pdst,
    float* __restrict__ out,
    int n_edges)
{
    const int t    = blockIdx.x * 256 + threadIdx.x;
    const int e    = t >> 4;
    const int lane = (t & 15) << 2;   // float offset within the 64-float row
    if (e >= n_edges) return;

    const int s = __ldg(&src[e]);
    const int d = __ldg(&dst[e]);

    const float4 a = *reinterpret_cast<const float4*>(&Psrc[s * D_OUT + lane]);
    const float4 c = *reinterpret_cast<const float4*>(&Pdst[d * D_OUT + lane]);

    float4 o;
    o.x = a.x + c.x;
    o.y = a.y + c.y;
    o.z = a.z + c.z;
    o.w = a.w + c.w;

    *reinterpret_cast<float4*>(&out[(size_t)e * D_OUT + lane]) = o;
}

// ---------------------------------------------------------------------------
// Launch: metadata order is x, W, b, src, dst
// ---------------------------------------------------------------------------
extern "C" void kernel_launch(void* const* d_in, const int* in_sizes, int n_in,
                              void* d_out, int out_size)
{
    const float* x   = (const float*)d_in[0];
    const float* W   = (const float*)d_in[1];
    const float* b   = (const float*)d_in[2];
    const int*   src = (const int*)d_in[3];
    const int*   dst = (const int*)d_in[4];
    float*       out = (float*)d_out;

    const int n_nodes = in_sizes[0] / D_FEAT;
    const int n_edges = in_sizes[3];

    float* Psrc; float* Pdst;
    cudaGetSymbolAddress((void**)&Psrc, g_Psrc);
    cudaGetSymbolAddress((void**)&Pdst, g_Pdst);

    const int blocks1 = (n_nodes + ROWS_PER_BLOCK - 1) / ROWS_PER_BLOCK;
    node_project_kernel<<<blocks1, 256>>>(x, W, b, n_nodes);

    const int blocks2 = (int)(((long long)n_edges * 16 + 255) / 256);
    edge_gather_kernel<<<blocks2, 256>>>(src, dst, Psrc, Pdst, out, n_edges);
}

// round 7
// speedup vs baseline: 1.5558x; 1.5558x over previous
#include <cuda_runtime.h>
#include <cstdint>

#define D_FEAT   64
#define D_OUT    64
#define MAX_NODES 50000
#define ROWS_PER_BLOCK 32
#define NP_THREADS 128
#define XT_STRIDE 36   // pad; (36*4) % 16 == 0 keeps float4 alignment

// Scratch: per-node projections (graph-capturable, no allocs)
__device__ float g_Psrc[MAX_NODES * D_OUT];
__device__ float g_Pdst[MAX_NODES * D_OUT];

// ---------------------------------------------------------------------------
// Kernel 1: per-node projections
//   Psrc[n][j] = x[n][:] @ W[0:64][j] + b[j]
//   Pdst[n][j] = x[n][:] @ W[64:128][j]
// 128 threads, 32 rows/block. Register tile: 8 rows x 2 cols x {src,dst}
// = 32 FFMA per (2 LDS.128 + 2 LDS.64). smem = 32KB (W) + 9.2KB (xT) < 48KB.
// Threads sharing r0 read identical xT addresses -> LDS broadcast, 0 conflicts.
// ---------------------------------------------------------------------------
__global__ __launch_bounds__(NP_THREADS) void node_project_kernel(
    const float* __restrict__ x,
    const float* __restrict__ W,
    const float* __restrict__ b,
    int n_nodes)
{
    __shared__ float Wsh[2 * D_FEAT * D_OUT];        // 32 KB
    __shared__ float xT[D_FEAT * XT_STRIDE];         // 9.2 KB, transposed tile

    const int tid  = threadIdx.x;
    const int row0 = blockIdx.x * ROWS_PER_BLOCK;

    // Stage W (row-major [128][64]) — float4 loads, 16 iters/thread
    #pragma unroll
    for (int i = tid; i < 2 * D_FEAT * D_OUT / 4; i += NP_THREADS)
        *reinterpret_cast<float4*>(&Wsh[i * 4]) =
            *reinterpret_cast<const float4*>(&W[i * 4]);

    // Stage x tile transposed: xT[k][r] = x[row0+r][k]; global read coalesced.
    #pragma unroll
    for (int i = tid; i < ROWS_PER_BLOCK * D_FEAT; i += NP_THREADS) {
        const int r = i >> 6;        // 0..31
        const int c = i & 63;        // 0..63
        float v = 0.0f;
        if (row0 + r < n_nodes) v = x[(row0 + r) * D_FEAT + c];
        xT[c * XT_STRIDE + r] = v;
    }
    __syncthreads();

    // Thread tile: rows r0..r0+7 (tid&3), cols c0..c0+1 (tid>>2)
    const int r0 = (tid & 3) << 3;      // 0,8,16,24
    const int c0 = (tid >> 2) << 1;     // 0,2,...,62

    float accS[8][2];
    float accD[8][2];
    #pragma unroll
    for (int i = 0; i < 8; i++) {
        accS[i][0] = accS[i][1] = 0.f;
        accD[i][0] = accD[i][1] = 0.f;
    }

    #pragma unroll 4
    for (int k = 0; k < D_FEAT; k++) {
        const float4 xa = *reinterpret_cast<const float4*>(&xT[k * XT_STRIDE + r0]);
        const float4 xb = *reinterpret_cast<const float4*>(&xT[k * XT_STRIDE + r0 + 4]);
        const float2 ws = *reinterpret_cast<const float2*>(&Wsh[k * D_OUT + c0]);
        const float2 wd = *reinterpret_cast<const float2*>(&Wsh[(D_FEAT + k) * D_OUT + c0]);
        const float xr[8] = {xa.x, xa.y, xa.z, xa.w, xb.x, xb.y, xb.z, xb.w};
        #pragma unroll
        for (int i = 0; i < 8; i++) {
            accS[i][0] += xr[i] * ws.x;
            accS[i][1] += xr[i] * ws.y;
            accD[i][0] += xr[i] * wd.x;
            accD[i][1] += xr[i] * wd.y;
        }
    }

    const float2 bv = *reinterpret_cast<const float2*>(&b[c0]);

    #pragma unroll
    for (int i = 0; i < 8; i++) {
        const int row = row0 + r0 + i;
        if (row < n_nodes) {
            *reinterpret_cast<float2*>(&g_Psrc[row * D_OUT + c0]) =
                make_float2(accS[i][0] + bv.x, accS[i][1] + bv.y);
            *reinterpret_cast<float2*>(&g_Pdst[row * D_OUT + c0]) =
                make_float2(accD[i][0], accD[i][1]);
        }
    }
}

// ---------------------------------------------------------------------------
// Kernel 2: edge gather-add. 16 threads per edge, 2 edges per thread per
// grid-stride iteration (4 independent gathers in flight). Streaming stores
// (__stcs) keep the 205 MB output stream from evicting the L2-resident
// P tables (25.6 MB, the thing that makes the gathers fast).
// ---------------------------------------------------------------------------
__global__ __launch_bounds__(256) void edge_gather_kernel(
    const int* __restrict__ src,
    const int* __restrict__ dst,
    const float* __restrict__ Psrc,
    const float* __restrict__ Pdst,
    float* __restrict__ out,
    int n_edges)
{
    const int t       = blockIdx.x * 256 + threadIdx.x;
    const int lane4   = (t & 15) << 2;              // float offset in the row
    const int ngroups = (gridDim.x * 256) >> 4;     // edge-pair groups
    const int n_pairs = (n_edges + 1) >> 1;

    for (int g = t >> 4; g < n_pairs; g += ngroups) {
        const int e0 = g * 2;
        const int e1 = e0 + 1;
        const bool has1 = (e1 < n_edges);

        // Issue all index loads
        const int s0 = __ldg(&src[e0]);
        const int d0 = __ldg(&dst[e0]);
        const int s1 = has1 ? __ldg(&src[e1]) : 0;
        const int d1 = has1 ? __ldg(&dst[e1]) : 0;

        // Issue all gathers (4 independent 16B loads in flight)
        const float4 a0 = *reinterpret_cast<const float4*>(&Psrc[s0 * D_OUT + lane4]);
        const float4 c0 = *reinterpret_cast<const float4*>(&Pdst[d0 * D_OUT + lane4]);
        const float4 a1 = *reinterpret_cast<const float4*>(&Psrc[s1 * D_OUT + lane4]);
        const float4 c1 = *reinterpret_cast<const float4*>(&Pdst[d1 * D_OUT + lane4]);

        float4 o0;
        o0.x = a0.x + c0.x; o0.y = a0.y + c0.y;
        o0.z = a0.z + c0.z; o0.w = a0.w + c0.w;
        __stcs(reinterpret_cast<float4*>(&out[(size_t)e0 * D_OUT + lane4]), o0);

        if (has1) {
            float4 o1;
            o1.x = a1.x + c1.x; o1.y = a1.y + c1.y;
            o1.z = a1.z + c1.z; o1.w = a1.w + c1.w;
            __stcs(reinterpret_cast<float4*>(&out[(size_t)e1 * D_OUT + lane4]), o1);
        }
    }
}

// ---------------------------------------------------------------------------
// Launch: metadata order is x, W, b, src, dst
// ---------------------------------------------------------------------------
extern "C" void kernel_launch(void* const* d_in, const int* in_sizes, int n_in,
                              void* d_out, int out_size)
{
    const float* x   = (const float*)d_in[0];
    const float* W   = (const float*)d_in[1];
    const float* b   = (const float*)d_in[2];
    const int*   src = (const int*)d_in[3];
    const int*   dst = (const int*)d_in[4];
    float*       out = (float*)d_out;

    const int n_nodes = in_sizes[0] / D_FEAT;
    const int n_edges = in_sizes[3];

    float* Psrc; float* Pdst;
    cudaGetSymbolAddress((void**)&Psrc, g_Psrc);
    cudaGetSymbolAddress((void**)&Pdst, g_Pdst);

    const int blocks1 = (n_nodes + ROWS_PER_BLOCK - 1) / ROWS_PER_BLOCK;
    node_project_kernel<<<blocks1, NP_THREADS>>>(x, W, b, n_nodes);

    // Bounded grid-stride: 2072 = 148 SMs * 14 CTAs, exact wave multiple.
    const int blocks2 = 148 * 14;
    edge_gather_kernel<<<blocks2, 256>>>(src, dst, Psrc, Pdst, out, n_edges);
}